// round 10
// baseline (speedup 1.0000x reference)
#include <cuda_runtime.h>
#include <cuda_bf16.h>
#include <cstdint>

// ---------------- problem constants ----------------
constexpr int BB = 4;
constexpr int LL = 2048;
constexpr int DM = 1024;
constexpr int DI = 2048;      // d_inner
constexpr int DS = 16;        // d_state
constexpr int MR = BB * LL;   // 8192 rows
constexpr int NXZ = 2 * DI;   // 4096

// ---------------- scratch (device globals; no allocation allowed) ----------------
__device__ float g_xz[(size_t)MR * NXZ];       // [xi | z]
__device__ float g_xiconv[(size_t)MR * DI];    // silu(conv(xi))
__device__ float g_dtraw[MR];
__device__ float g_Bc[MR * DS];
__device__ float g_Cc[MR * DS];
__device__ float g_y[(size_t)MR * DI];

// bf16 hi/lo split operands for the tensor-core GEMMs
__device__ __nv_bfloat16 g_xh [(size_t)MR * DM];
__device__ __nv_bfloat16 g_xl [(size_t)MR * DM];
__device__ __nv_bfloat16 g_wih[(size_t)NXZ * DM];
__device__ __nv_bfloat16 g_wil[(size_t)NXZ * DM];
__device__ __nv_bfloat16 g_oph[(size_t)MR * DI];
__device__ __nv_bfloat16 g_opl[(size_t)MR * DI];
__device__ __nv_bfloat16 g_woh[(size_t)DM * DI];
__device__ __nv_bfloat16 g_wol[(size_t)DM * DI];

// ============================================================================
// PTX helpers (portable sm_80+ subset only — NO tcgen05 on this build target)
// ============================================================================
__device__ __forceinline__ uint32_t smem_u32(const void* p) {
    uint32_t a;
    asm("{ .reg .u64 t; cvta.to.shared.u64 t, %1; cvt.u32.u64 %0, t; }" : "=r"(a) : "l"(p));
    return a;
}
__device__ __forceinline__ void cp_async16(uint32_t dst, const void* src) {
    asm volatile("cp.async.cg.shared.global [%0], [%1], 16;" :: "r"(dst), "l"(src));
}
__device__ __forceinline__ void cp_commit() { asm volatile("cp.async.commit_group;"); }
template<int N> __device__ __forceinline__ void cp_wait() {
    asm volatile("cp.async.wait_group %0;" :: "n"(N));
}
__device__ __forceinline__ void ldmx4(uint32_t& r0, uint32_t& r1, uint32_t& r2, uint32_t& r3,
                                      uint32_t addr) {
    asm volatile("ldmatrix.sync.aligned.m8n8.x4.shared.b16 {%0,%1,%2,%3}, [%4];"
                 : "=r"(r0), "=r"(r1), "=r"(r2), "=r"(r3) : "r"(addr));
}
__device__ __forceinline__ void mma_bf16(float* c, const uint32_t* a, const uint32_t* b) {
    asm volatile(
        "mma.sync.aligned.m16n8k16.row.col.f32.bf16.bf16.f32 "
        "{%0,%1,%2,%3}, {%4,%5,%6,%7}, {%8,%9}, {%0,%1,%2,%3};"
        : "+f"(c[0]), "+f"(c[1]), "+f"(c[2]), "+f"(c[3])
        : "r"(a[0]), "r"(a[1]), "r"(a[2]), "r"(a[3]), "r"(b[0]), "r"(b[1]));
}
// SW64 swizzle on byte offsets within a (128-row x 64B) tile. 16B-granular.
__device__ __forceinline__ uint32_t swz64(uint32_t off) {
    return off ^ ((off >> 3) & 0x30);
}

// ============================================================================
// bf16-split mma.sync GEMM (EXACT R6 schedule — verified local optimum):
// Block 128x128, BK=32, 8 warps (2x4), warp tile 64x32.
// SW64-swizzled 64B rows; 3-stage cp.async; per-kk B loads; load AFTER compute.
// ============================================================================
constexpr int ROWB   = 64;
constexpr int TILEB  = 128 * ROWB;          // 8192 per operand tile
constexpr int STAGEB = 4 * TILEB;           // 32768
constexpr int NSTAGE = 3;
constexpr int GEMM_SMEM = NSTAGE * STAGEB;  // 98304

template<int Ktot>
__device__ __forceinline__ void load_stage(uint32_t stage, int k0, int bm0, int bn0,
                                           const __nv_bfloat16* __restrict__ Ah,
                                           const __nv_bfloat16* __restrict__ Al,
                                           const __nv_bfloat16* __restrict__ Bh,
                                           const __nv_bfloat16* __restrict__ Bl,
                                           int tid) {
    const __nv_bfloat16* srcs[4] = {Ah, Al, Bh, Bl};
    const int row0s[2] = {bm0, bn0};
    #pragma unroll
    for (int i = 0; i < 8; i++) {
        int u = tid + i * 256;
        int s = u >> 9;
        int v = u & 511;
        int r = v >> 2, c = v & 3;
        cp_async16(stage + s * TILEB + swz64(r * ROWB + c * 16),
                   srcs[s] + (size_t)(row0s[s >> 1] + r) * Ktot + k0 + c * 8);
    }
    cp_commit();
}

template<int Ntot, int Ktot>
__global__ void __launch_bounds__(256) gemm_mma(const __nv_bfloat16* __restrict__ Ah,
                                                const __nv_bfloat16* __restrict__ Al,
                                                const __nv_bfloat16* __restrict__ Bh,
                                                const __nv_bfloat16* __restrict__ Bl,
                                                float* __restrict__ C) {
    extern __shared__ char smem[];
    const uint32_t sb = smem_u32(smem);
    const int tid  = threadIdx.x;
    const int wid  = tid >> 5, lane = tid & 31;
    const int wm   = wid >> 2;
    const int wn   = wid & 3;
    const int bm0  = blockIdx.y * 128;
    const int bn0  = blockIdx.x * 128;
    constexpr int NCHUNK = Ktot / 32;

    float acc[4][4][4];
    #pragma unroll
    for (int i = 0; i < 4; i++)
        #pragma unroll
        for (int j = 0; j < 4; j++)
            #pragma unroll
            for (int q = 0; q < 4; q++) acc[i][j][q] = 0.f;

    const int lrow  = lane & 15;
    const int khalf = (lane >> 4) * 16;
    const uint32_t aRow = (wm * 64 + lrow) * ROWB;
    const uint32_t bRow = (wn * 32 + lrow) * ROWB;

    load_stage<Ktot>(sb, 0, bm0, bn0, Ah, Al, Bh, Bl, tid);
    load_stage<Ktot>(sb + STAGEB, 32, bm0, bn0, Ah, Al, Bh, Bl, tid);

    uint32_t stOff = 0;
    uint32_t ldOff = 2 * STAGEB;

    for (int k = 0; k < NCHUNK; k++) {
        if (k + 1 < NCHUNK) cp_wait<1>(); else cp_wait<0>();
        __syncthreads();

        const uint32_t st = sb + stOff;
        #pragma unroll
        for (int kk = 0; kk < 32; kk += 16) {
            const uint32_t kbyte = kk * 2 + khalf;
            uint32_t bh[8], bl[8];
            #pragma unroll
            for (int nj = 0; nj < 2; nj++) {
                uint32_t a = st + 2 * TILEB + swz64(bRow + nj * 16 * ROWB + kbyte);
                ldmx4(bh[nj * 4 + 0], bh[nj * 4 + 1], bh[nj * 4 + 2], bh[nj * 4 + 3], a);
                ldmx4(bl[nj * 4 + 0], bl[nj * 4 + 1], bl[nj * 4 + 2], bl[nj * 4 + 3], a + TILEB);
            }
            #pragma unroll
            for (int mi = 0; mi < 4; mi++) {
                uint32_t ah[4], al[4];
                uint32_t a = st + swz64(aRow + mi * 16 * ROWB + kbyte);
                ldmx4(ah[0], ah[1], ah[2], ah[3], a);
                ldmx4(al[0], al[1], al[2], al[3], a + TILEB);
                #pragma unroll
                for (int ni = 0; ni < 4; ni++) {
                    const int g = (ni >> 1) * 4 + (ni & 1);
                    uint32_t bhp[2] = {bh[g], bh[g + 2]};
                    uint32_t blp[2] = {bl[g], bl[g + 2]};
                    mma_bf16(acc[mi][ni], ah, bhp);
                    mma_bf16(acc[mi][ni], ah, blp);
                    mma_bf16(acc[mi][ni], al, bhp);
                }
            }
        }
        if (k + 2 < NCHUNK) {
            load_stage<Ktot>(sb + ldOff, (k + 2) * 32, bm0, bn0, Ah, Al, Bh, Bl, tid);
            ldOff += STAGEB; if (ldOff == NSTAGE * STAGEB) ldOff = 0;
        }
        stOff += STAGEB; if (stOff == NSTAGE * STAGEB) stOff = 0;
    }

    #pragma unroll
    for (int mi = 0; mi < 4; mi++) {
        const int r0 = bm0 + wm * 64 + mi * 16 + (lane >> 2);
        #pragma unroll
        for (int ni = 0; ni < 4; ni++) {
            const int c = bn0 + wn * 32 + ni * 8 + (lane & 3) * 2;
            *(float2*)(C + (size_t)r0 * Ntot + c) =
                make_float2(acc[mi][ni][0], acc[mi][ni][1]);
            *(float2*)(C + (size_t)(r0 + 8) * Ntot + c) =
                make_float2(acc[mi][ni][2], acc[mi][ni][3]);
        }
    }
}

// ============================================================================
// fp32 -> bf16 hi/lo split (4 elements / thread)
// ============================================================================
__global__ void __launch_bounds__(256) split_kernel(const float* __restrict__ in,
                                                    __nv_bfloat16* __restrict__ hi,
                                                    __nv_bfloat16* __restrict__ lo,
                                                    int n4) {
    int i = blockIdx.x * 256 + threadIdx.x;
    if (i >= n4) return;
    float4 v = *(const float4*)(in + (size_t)i * 4);
    float vv[4] = {v.x, v.y, v.z, v.w};
    __nv_bfloat16 h[4], l[4];
    #pragma unroll
    for (int q = 0; q < 4; q++) {
        h[q] = __float2bfloat16(vv[q]);
        l[q] = __float2bfloat16(vv[q] - __bfloat162float(h[q]));
    }
    *(uint2*)(hi + (size_t)i * 4) = *(uint2*)h;
    *(uint2*)(lo + (size_t)i * 4) = *(uint2*)l;
}

// ============================================================================
// projx with FUSED conv+silu: stages 8 rows of silu(conv(xz)) into smem
// (writing g_xiconv on the way), then computes xd = xi @ W_x^T (N=33).
// Replaces the separate conv_silu kernel (saves one 64MB pass + a launch).
// ============================================================================
constexpr int PRJ_ROWS = 8;
constexpr int PRJ_SMEM = PRJ_ROWS * DI * 4;   // 65536

__global__ void __launch_bounds__(256) projx_kernel(const float* __restrict__ W_x,
                                                    const float* __restrict__ conv_w,
                                                    const float* __restrict__ conv_b) {
    extern __shared__ float xs[];             // [PRJ_ROWS][DI]
    const int m0 = blockIdx.x * PRJ_ROWS;

    // fused conv + silu staging
    for (int i = threadIdx.x; i < PRJ_ROWS * DI; i += 256) {
        const int r = i >> 11, c = i & (DI - 1);
        const int m = m0 + r;
        const int l = m & (LL - 1);
        float4 w4 = *(const float4*)(conv_w + c * 4);
        float w[4] = {w4.x, w4.y, w4.z, w4.w};
        const float* base = g_xz + (size_t)m * NXZ + c;
        float s = conv_b[c];
        #pragma unroll
        for (int t = 0; t < 4; t++) {
            if (l - 3 + t >= 0) s += base[(ptrdiff_t)(t - 3) * NXZ] * w[t];
        }
        float sv = s * (1.f / (1.f + __expf(-s)));
        xs[r * DI + c] = sv;
        g_xiconv[(size_t)m * DI + c] = sv;
    }
    __syncthreads();

    const int warp = threadIdx.x >> 5;
    const int lane = threadIdx.x & 31;
    for (int g = warp; g < 9; g += 8) {
        const int nbase = g * 4;
        const int ncnt  = (g == 8) ? 1 : 4;
        float acc[4][PRJ_ROWS];
        #pragma unroll
        for (int a = 0; a < 4; a++)
            #pragma unroll
            for (int r = 0; r < PRJ_ROWS; r++) acc[a][r] = 0.f;

        for (int k = lane * 4; k < DI; k += 128) {
            float4 xr[PRJ_ROWS];
            #pragma unroll
            for (int r = 0; r < PRJ_ROWS; r++) xr[r] = *(const float4*)&xs[r * DI + k];
            for (int nn = 0; nn < ncnt; nn++) {
                float4 wv = *(const float4*)(W_x + (size_t)(nbase + nn) * DI + k);
                #pragma unroll
                for (int r = 0; r < PRJ_ROWS; r++) {
                    acc[nn][r] += wv.x * xr[r].x + wv.y * xr[r].y
                                + wv.z * xr[r].z + wv.w * xr[r].w;
                }
            }
        }
        for (int nn = 0; nn < ncnt; nn++) {
            #pragma unroll
            for (int r = 0; r < PRJ_ROWS; r++) {
                float v = acc[nn][r];
                #pragma unroll
                for (int off = 16; off; off >>= 1)
                    v += __shfl_xor_sync(0xffffffffu, v, off);
                acc[nn][r] = v;
            }
            if (lane == 0) {
                const int n = nbase + nn;
                #pragma unroll
                for (int r = 0; r < PRJ_ROWS; r++) {
                    int m = m0 + r;
                    if (n == 0)            g_dtraw[m] = acc[nn][r];
                    else if (n < 1 + DS)   g_Bc[m * DS + (n - 1)] = acc[nn][r];
                    else                   g_Cc[m * DS + (n - 1 - DS)] = acc[nn][r];
                }
            }
        }
    }
}

// ============================================================================
// selective scan: 8 threads per (b,d) channel, 2 states each, 8-deep register
// prefetch. Dense dt: per 8-step block, each lane computes softplus for its
// OWN channel at u == its sub index (32/32-lane dense, 1x work instead of 8x
// redundant), then steps fetch dt via intra-group shfl. Bit-identical math.
// ============================================================================
__global__ void __launch_bounds__(256) scan_kernel(const float* __restrict__ A_log,
                                                   const float* __restrict__ W_dt,
                                                   const float* __restrict__ b_dt) {
    const int lane = threadIdx.x & 31;
    const int sub  = threadIdx.x & 7;       // 8 subs per channel (== u index)
    const int dloc = threadIdx.x >> 3;      // 32 channels per block
    const int d    = blockIdx.x * 32 + dloc;
    const int b    = blockIdx.y;
    const int s0   = sub * 2;
    const int grpBase = lane & 24;          // first lane of this channel's group

    float Ac[2];
    #pragma unroll
    for (int i = 0; i < 2; i++) Ac[i] = -__expf(fminf(A_log[s0 + i], 5.f));
    const float Wd = W_dt[d];
    const float bd = b_dt[d];

    float h[2] = {0.f, 0.f};

    const size_t mbase = (size_t)b * LL;
    constexpr int PF = 8;
    float  dr_b[PF], xv_b[PF];
    float2 Bv_b[PF], Cv_b[PF];
    #pragma unroll
    for (int u = 0; u < PF; u++) {
        size_t m = mbase + u;
        dr_b[u] = g_dtraw[m];
        xv_b[u] = g_xiconv[m * DI + d];
        Bv_b[u] = *(const float2*)(g_Bc + m * DS + s0);
        Cv_b[u] = *(const float2*)(g_Cc + m * DS + s0);
    }

    for (int l0 = 0; l0 < LL; l0 += PF) {
        // dense dt precompute: this lane handles u == sub for its own channel
        float myDr = dr_b[0];
        #pragma unroll
        for (int u = 1; u < PF; u++) if (sub == u) myDr = dr_b[u];
        float xx = myDr * Wd + bd;
        float sp = fmaxf(xx, 0.f) + __logf(1.f + __expf(-fabsf(xx)));
        float myDt = fminf(fmaxf(sp, 1e-4f), 10.f);

        #pragma unroll
        for (int u = 0; u < PF; u++) {
            const int l = l0 + u;
            const float  xv = xv_b[u];
            const float2 Bq = Bv_b[u], Cq = Cv_b[u];
            const float dt = __shfl_sync(0xffffffffu, myDt, grpBase + u);

            const int lp = l + PF;
            if (lp < LL) {
                size_t mp = mbase + lp;
                dr_b[u] = g_dtraw[mp];
                xv_b[u] = g_xiconv[mp * DI + d];
                Bv_b[u] = *(const float2*)(g_Bc + mp * DS + s0);
                Cv_b[u] = *(const float2*)(g_Cc + mp * DS + s0);
            }

            float Bv[2] = {Bq.x, Bq.y};
            float Cv[2] = {Cq.x, Cq.y};
            float y = 0.f;
            #pragma unroll
            for (int i = 0; i < 2; i++) {
                // dt>0, Ac<0 -> dt*Ac<0 always; only the -20 clamp can bind
                float dA  = __expf(fmaxf(dt * Ac[i], -20.f));
                float dBu = fminf(fmaxf(dt * Bv[i] * xv, -10.f), 10.f);
                h[i] = fminf(fmaxf(h[i] * dA + dBu, -100.f), 100.f);
                y += h[i] * Cv[i];
            }
            y += __shfl_xor_sync(0xffffffffu, y, 1);
            y += __shfl_xor_sync(0xffffffffu, y, 2);
            y += __shfl_xor_sync(0xffffffffu, y, 4);
            if (sub == 0) g_y[(mbase + l) * DI + d] = y;
        }
    }
}

// ============================================================================
// layernorm(y) -> (yn + D*xi) * silu(z) -> bf16 hi/lo. y row cached in regs.
// ============================================================================
__device__ __forceinline__ float block_reduce_sum(float v) {
    __shared__ float sh[8];
    __syncthreads();
    int lane = threadIdx.x & 31, w = threadIdx.x >> 5;
    #pragma unroll
    for (int o = 16; o; o >>= 1) v += __shfl_xor_sync(0xffffffffu, v, o);
    if (lane == 0) sh[w] = v;
    __syncthreads();
    if (threadIdx.x < 32) {
        v = (threadIdx.x < 8) ? sh[threadIdx.x] : 0.f;
        #pragma unroll
        for (int o = 4; o; o >>= 1) v += __shfl_xor_sync(0xffffffffu, v, o);
        if (threadIdx.x == 0) sh[0] = v;
    }
    __syncthreads();
    return sh[0];
}

__global__ void __launch_bounds__(256) lncomb_kernel(const float* __restrict__ ln_w,
                                                     const float* __restrict__ ln_b,
                                                     const float* __restrict__ D_param) {
    const int m = blockIdx.x;
    const float* yrow = g_y + (size_t)m * DI;

    float4 yv[2];
    float s = 0.f;
    #pragma unroll
    for (int j = 0; j < 2; j++) {
        yv[j] = *(const float4*)(yrow + j * 1024 + threadIdx.x * 4);
        s += yv[j].x + yv[j].y + yv[j].z + yv[j].w;
    }
    float mu = block_reduce_sum(s) * (1.f / DI);

    float v = 0.f;
    #pragma unroll
    for (int j = 0; j < 2; j++) {
        float t0 = yv[j].x - mu, t1 = yv[j].y - mu, t2 = yv[j].z - mu, t3 = yv[j].w - mu;
        v += t0 * t0 + t1 * t1 + t2 * t2 + t3 * t3;
    }
    float var = block_reduce_sum(v) * (1.f / DI);
    float rstd = rsqrtf(var + 1e-5f);

    #pragma unroll
    for (int j = 0; j < 2; j++) {
        const int dd = j * 1024 + threadIdx.x * 4;
        float4 lw = *(const float4*)(ln_w + dd);
        float4 lb = *(const float4*)(ln_b + dd);
        float4 Dp = *(const float4*)(D_param + dd);
        float4 xi = *(const float4*)(g_xiconv + (size_t)m * DI + dd);
        float4 zz = *(const float4*)(g_xz + (size_t)m * NXZ + DI + dd);
        float yy[4] = {yv[j].x, yv[j].y, yv[j].z, yv[j].w};
        float lww[4] = {lw.x, lw.y, lw.z, lw.w};
        float lbb[4] = {lb.x, lb.y, lb.z, lb.w};
        float dpp[4] = {Dp.x, Dp.y, Dp.z, Dp.w};
        float xii[4] = {xi.x, xi.y, xi.z, xi.w};
        float zzz[4] = {zz.x, zz.y, zz.z, zz.w};
        __nv_bfloat16 hh[4], ll[4];
        #pragma unroll
        for (int q = 0; q < 4; q++) {
            float yn = (yy[q] - mu) * rstd * lww[q] + lbb[q];
            float sz = zzz[q] * (1.f / (1.f + __expf(-zzz[q])));
            float val = (yn + dpp[q] * xii[q]) * sz;
            hh[q] = __float2bfloat16(val);
            ll[q] = __float2bfloat16(val - __bfloat162float(hh[q]));
        }
        *(uint2*)(g_oph + (size_t)m * DI + dd) = *(uint2*)hh;
        *(uint2*)(g_opl + (size_t)m * DI + dd) = *(uint2*)ll;
    }
}

// ============================================================================
// launch
// ============================================================================
extern "C" void kernel_launch(void* const* d_in, const int* in_sizes, int n_in,
                              void* d_out, int out_size) {
    (void)in_sizes; (void)n_in; (void)out_size;
    const float* x       = (const float*)d_in[0];
    const float* W_in    = (const float*)d_in[1];
    const float* conv_w  = (const float*)d_in[2];
    const float* conv_b  = (const float*)d_in[3];
    const float* W_x     = (const float*)d_in[4];
    const float* W_dt    = (const float*)d_in[5];
    const float* b_dt    = (const float*)d_in[6];
    const float* A_log   = (const float*)d_in[7];
    const float* D_param = (const float*)d_in[8];
    const float* W_out   = (const float*)d_in[9];
    const float* ln_w    = (const float*)d_in[10];
    const float* ln_b    = (const float*)d_in[11];
    float* out = (float*)d_out;

    static __nv_bfloat16 *p_xh = nullptr, *p_xl, *p_wih, *p_wil, *p_oph, *p_opl, *p_woh, *p_wol;
    static float *p_xz = nullptr;
    if (!p_xh) {
        cudaGetSymbolAddress((void**)&p_xh,  g_xh);
        cudaGetSymbolAddress((void**)&p_xl,  g_xl);
        cudaGetSymbolAddress((void**)&p_wih, g_wih);
        cudaGetSymbolAddress((void**)&p_wil, g_wil);
        cudaGetSymbolAddress((void**)&p_oph, g_oph);
        cudaGetSymbolAddress((void**)&p_opl, g_opl);
        cudaGetSymbolAddress((void**)&p_woh, g_woh);
        cudaGetSymbolAddress((void**)&p_wol, g_wol);
        cudaGetSymbolAddress((void**)&p_xz,  g_xz);
        cudaFuncSetAttribute(gemm_mma<NXZ, DM>,
                             cudaFuncAttributeMaxDynamicSharedMemorySize, GEMM_SMEM);
        cudaFuncSetAttribute(gemm_mma<DM, DI>,
                             cudaFuncAttributeMaxDynamicSharedMemorySize, GEMM_SMEM);
        cudaFuncSetAttribute(projx_kernel,
                             cudaFuncAttributeMaxDynamicSharedMemorySize, PRJ_SMEM);
    }

    // 0) fp32 -> bf16 hi/lo splits
    split_kernel<<<(MR * DM / 4 + 255) / 256, 256>>>(x, p_xh, p_xl, MR * DM / 4);
    split_kernel<<<(NXZ * DM / 4 + 255) / 256, 256>>>(W_in, p_wih, p_wil, NXZ * DM / 4);
    split_kernel<<<(DM * DI / 4 + 255) / 256, 256>>>(W_out, p_woh, p_wol, DM * DI / 4);

    // 1) xz = x @ W_in^T   (mma.sync, bf16-split)
    {
        dim3 grid(NXZ / 128, MR / 128);
        gemm_mma<NXZ, DM><<<grid, 256, GEMM_SMEM>>>(p_xh, p_xl, p_wih, p_wil, p_xz);
    }
    // 2) projx with fused conv+silu (writes g_xiconv, g_dtraw, g_Bc, g_Cc)
    projx_kernel<<<MR / PRJ_ROWS, 256, PRJ_SMEM>>>(W_x, conv_w, conv_b);
    // 3) sequential selective scan (dense dt)
    {
        dim3 grid(DI / 32, BB);
        scan_kernel<<<grid, 256>>>(A_log, W_dt, b_dt);
    }
    // 4) layernorm + combine (writes bf16 hi/lo outpre)
    lncomb_kernel<<<MR, 256>>>(ln_w, ln_b, D_param);
    // 5) out = outpre @ W_out^T   (mma.sync, bf16-split)
    {
        dim3 grid(DM / 128, MR / 128);
        gemm_mma<DM, DI><<<grid, 256, GEMM_SMEM>>>(p_oph, p_opl, p_woh, p_wol, out);
    }
}

// round 11
// speedup vs baseline: 1.0184x; 1.0184x over previous
#include <cuda_runtime.h>
#include <cuda_bf16.h>
#include <cstdint>

// ---------------- problem constants ----------------
constexpr int BB = 4;
constexpr int LL = 2048;
constexpr int DM = 1024;
constexpr int DI = 2048;      // d_inner
constexpr int DS = 16;        // d_state
constexpr int MR = BB * LL;   // 8192 rows
constexpr int NXZ = 2 * DI;   // 4096

// ---------------- scratch (device globals; no allocation allowed) ----------------
__device__ float g_xz[(size_t)MR * NXZ];       // [xi | z]
__device__ float g_xiconv[(size_t)MR * DI];    // silu(conv(xi))
__device__ float g_dtraw[MR];
__device__ float g_Bc[MR * DS];
__device__ float g_Cc[MR * DS];
__device__ float g_y[(size_t)MR * DI];

// bf16 hi/lo split operands for the tensor-core GEMMs
__device__ __nv_bfloat16 g_xh [(size_t)MR * DM];
__device__ __nv_bfloat16 g_xl [(size_t)MR * DM];
__device__ __nv_bfloat16 g_wih[(size_t)NXZ * DM];
__device__ __nv_bfloat16 g_wil[(size_t)NXZ * DM];
__device__ __nv_bfloat16 g_oph[(size_t)MR * DI];
__device__ __nv_bfloat16 g_opl[(size_t)MR * DI];
__device__ __nv_bfloat16 g_woh[(size_t)DM * DI];
__device__ __nv_bfloat16 g_wol[(size_t)DM * DI];

// ============================================================================
// PTX helpers (portable sm_80+ subset only — NO tcgen05 on this build target)
// ============================================================================
__device__ __forceinline__ uint32_t smem_u32(const void* p) {
    uint32_t a;
    asm("{ .reg .u64 t; cvta.to.shared.u64 t, %1; cvt.u32.u64 %0, t; }" : "=r"(a) : "l"(p));
    return a;
}
__device__ __forceinline__ void cp_async16(uint32_t dst, const void* src) {
    asm volatile("cp.async.cg.shared.global [%0], [%1], 16;" :: "r"(dst), "l"(src));
}
__device__ __forceinline__ void cp_commit() { asm volatile("cp.async.commit_group;"); }
template<int N> __device__ __forceinline__ void cp_wait() {
    asm volatile("cp.async.wait_group %0;" :: "n"(N));
}
__device__ __forceinline__ void ldmx4(uint32_t& r0, uint32_t& r1, uint32_t& r2, uint32_t& r3,
                                      uint32_t addr) {
    asm volatile("ldmatrix.sync.aligned.m8n8.x4.shared.b16 {%0,%1,%2,%3}, [%4];"
                 : "=r"(r0), "=r"(r1), "=r"(r2), "=r"(r3) : "r"(addr));
}
__device__ __forceinline__ void mma_bf16(float* c, const uint32_t* a, const uint32_t* b) {
    asm volatile(
        "mma.sync.aligned.m16n8k16.row.col.f32.bf16.bf16.f32 "
        "{%0,%1,%2,%3}, {%4,%5,%6,%7}, {%8,%9}, {%0,%1,%2,%3};"
        : "+f"(c[0]), "+f"(c[1]), "+f"(c[2]), "+f"(c[3])
        : "r"(a[0]), "r"(a[1]), "r"(a[2]), "r"(a[3]), "r"(b[0]), "r"(b[1]));
}
// SW64 swizzle on byte offsets within a (128-row x 64B) tile. 16B-granular.
__device__ __forceinline__ uint32_t swz64(uint32_t off) {
    return off ^ ((off >> 3) & 0x30);
}

// ============================================================================
// bf16-split mma.sync GEMM (EXACT R6 schedule — verified local optimum):
// Block 128x128, BK=32, 8 warps (2x4), warp tile 64x32.
// SW64-swizzled 64B rows; 3-stage cp.async; per-kk B loads; load AFTER compute.
// ============================================================================
constexpr int ROWB   = 64;
constexpr int TILEB  = 128 * ROWB;          // 8192 per operand tile
constexpr int STAGEB = 4 * TILEB;           // 32768
constexpr int NSTAGE = 3;
constexpr int GEMM_SMEM = NSTAGE * STAGEB;  // 98304

template<int Ktot>
__device__ __forceinline__ void load_stage(uint32_t stage, int k0, int bm0, int bn0,
                                           const __nv_bfloat16* __restrict__ Ah,
                                           const __nv_bfloat16* __restrict__ Al,
                                           const __nv_bfloat16* __restrict__ Bh,
                                           const __nv_bfloat16* __restrict__ Bl,
                                           int tid) {
    const __nv_bfloat16* srcs[4] = {Ah, Al, Bh, Bl};
    const int row0s[2] = {bm0, bn0};
    #pragma unroll
    for (int i = 0; i < 8; i++) {
        int u = tid + i * 256;
        int s = u >> 9;
        int v = u & 511;
        int r = v >> 2, c = v & 3;
        cp_async16(stage + s * TILEB + swz64(r * ROWB + c * 16),
                   srcs[s] + (size_t)(row0s[s >> 1] + r) * Ktot + k0 + c * 8);
    }
    cp_commit();
}

template<int Ntot, int Ktot>
__global__ void __launch_bounds__(256) gemm_mma(const __nv_bfloat16* __restrict__ Ah,
                                                const __nv_bfloat16* __restrict__ Al,
                                                const __nv_bfloat16* __restrict__ Bh,
                                                const __nv_bfloat16* __restrict__ Bl,
                                                float* __restrict__ C) {
    extern __shared__ char smem[];
    const uint32_t sb = smem_u32(smem);
    const int tid  = threadIdx.x;
    const int wid  = tid >> 5, lane = tid & 31;
    const int wm   = wid >> 2;
    const int wn   = wid & 3;
    const int bm0  = blockIdx.y * 128;
    const int bn0  = blockIdx.x * 128;
    constexpr int NCHUNK = Ktot / 32;

    float acc[4][4][4];
    #pragma unroll
    for (int i = 0; i < 4; i++)
        #pragma unroll
        for (int j = 0; j < 4; j++)
            #pragma unroll
            for (int q = 0; q < 4; q++) acc[i][j][q] = 0.f;

    const int lrow  = lane & 15;
    const int khalf = (lane >> 4) * 16;
    const uint32_t aRow = (wm * 64 + lrow) * ROWB;
    const uint32_t bRow = (wn * 32 + lrow) * ROWB;

    load_stage<Ktot>(sb, 0, bm0, bn0, Ah, Al, Bh, Bl, tid);
    load_stage<Ktot>(sb + STAGEB, 32, bm0, bn0, Ah, Al, Bh, Bl, tid);

    uint32_t stOff = 0;
    uint32_t ldOff = 2 * STAGEB;

    for (int k = 0; k < NCHUNK; k++) {
        if (k + 1 < NCHUNK) cp_wait<1>(); else cp_wait<0>();
        __syncthreads();

        const uint32_t st = sb + stOff;
        #pragma unroll
        for (int kk = 0; kk < 32; kk += 16) {
            const uint32_t kbyte = kk * 2 + khalf;
            uint32_t bh[8], bl[8];
            #pragma unroll
            for (int nj = 0; nj < 2; nj++) {
                uint32_t a = st + 2 * TILEB + swz64(bRow + nj * 16 * ROWB + kbyte);
                ldmx4(bh[nj * 4 + 0], bh[nj * 4 + 1], bh[nj * 4 + 2], bh[nj * 4 + 3], a);
                ldmx4(bl[nj * 4 + 0], bl[nj * 4 + 1], bl[nj * 4 + 2], bl[nj * 4 + 3], a + TILEB);
            }
            #pragma unroll
            for (int mi = 0; mi < 4; mi++) {
                uint32_t ah[4], al[4];
                uint32_t a = st + swz64(aRow + mi * 16 * ROWB + kbyte);
                ldmx4(ah[0], ah[1], ah[2], ah[3], a);
                ldmx4(al[0], al[1], al[2], al[3], a + TILEB);
                #pragma unroll
                for (int ni = 0; ni < 4; ni++) {
                    const int g = (ni >> 1) * 4 + (ni & 1);
                    uint32_t bhp[2] = {bh[g], bh[g + 2]};
                    uint32_t blp[2] = {bl[g], bl[g + 2]};
                    mma_bf16(acc[mi][ni], ah, bhp);
                    mma_bf16(acc[mi][ni], ah, blp);
                    mma_bf16(acc[mi][ni], al, bhp);
                }
            }
        }
        if (k + 2 < NCHUNK) {
            load_stage<Ktot>(sb + ldOff, (k + 2) * 32, bm0, bn0, Ah, Al, Bh, Bl, tid);
            ldOff += STAGEB; if (ldOff == NSTAGE * STAGEB) ldOff = 0;
        }
        stOff += STAGEB; if (stOff == NSTAGE * STAGEB) stOff = 0;
    }

    #pragma unroll
    for (int mi = 0; mi < 4; mi++) {
        const int r0 = bm0 + wm * 64 + mi * 16 + (lane >> 2);
        #pragma unroll
        for (int ni = 0; ni < 4; ni++) {
            const int c = bn0 + wn * 32 + ni * 8 + (lane & 3) * 2;
            *(float2*)(C + (size_t)r0 * Ntot + c) =
                make_float2(acc[mi][ni][0], acc[mi][ni][1]);
            *(float2*)(C + (size_t)(r0 + 8) * Ntot + c) =
                make_float2(acc[mi][ni][2], acc[mi][ni][3]);
        }
    }
}

// ============================================================================
// merged fp32 -> bf16 hi/lo split for x, W_in, W_out in ONE launch
// ============================================================================
constexpr int N4_X  = MR * DM / 4;     // 2M float4s
constexpr int N4_WI = NXZ * DM / 4;    // 1M
constexpr int N4_WO = DM * DI / 4;     // 512K
constexpr int N4_TOT = N4_X + N4_WI + N4_WO;

__global__ void __launch_bounds__(256) split_all_kernel(const float* __restrict__ x,
                                                        const float* __restrict__ W_in,
                                                        const float* __restrict__ W_out,
                                                        __nv_bfloat16* __restrict__ xh,
                                                        __nv_bfloat16* __restrict__ xl,
                                                        __nv_bfloat16* __restrict__ wih,
                                                        __nv_bfloat16* __restrict__ wil,
                                                        __nv_bfloat16* __restrict__ woh,
                                                        __nv_bfloat16* __restrict__ wol) {
    int i = blockIdx.x * 256 + threadIdx.x;
    if (i >= N4_TOT) return;
    const float* src;
    __nv_bfloat16 *hi, *lo;
    int j;
    if (i < N4_X)            { src = x;     hi = xh;  lo = xl;  j = i; }
    else if (i < N4_X + N4_WI) { src = W_in;  hi = wih; lo = wil; j = i - N4_X; }
    else                     { src = W_out; hi = woh; lo = wol; j = i - N4_X - N4_WI; }

    float4 v = *(const float4*)(src + (size_t)j * 4);
    float vv[4] = {v.x, v.y, v.z, v.w};
    __nv_bfloat16 h[4], l[4];
    #pragma unroll
    for (int q = 0; q < 4; q++) {
        h[q] = __float2bfloat16(vv[q]);
        l[q] = __float2bfloat16(vv[q] - __bfloat162float(h[q]));
    }
    *(uint2*)(hi + (size_t)j * 4) = *(uint2*)h;
    *(uint2*)(lo + (size_t)j * 4) = *(uint2*)l;
}

// ============================================================================
// causal depthwise conv (k=4, pad left 3) + bias + silu   (R6-verified form)
// ============================================================================
__global__ void __launch_bounds__(256) conv_silu_kernel(const float* __restrict__ conv_w,
                                                        const float* __restrict__ conv_b) {
    int idx = blockIdx.x * 256 + threadIdx.x;
    if (idx >= MR * DI) return;
    int c = idx & (DI - 1);
    int m = idx >> 11;
    int l = m & (LL - 1);

    float4 w4 = *(const float4*)(conv_w + c * 4);
    float w[4] = {w4.x, w4.y, w4.z, w4.w};
    const float* base = g_xz + (size_t)m * NXZ + c;
    float s = conv_b[c];
    #pragma unroll
    for (int t = 0; t < 4; t++) {
        int ll = l - 3 + t;
        if (ll >= 0) s += base[(ptrdiff_t)(t - 3) * NXZ] * w[t];
    }
    float sv = s * (1.f / (1.f + __expf(-s)));
    g_xiconv[idx] = sv;
}

// ============================================================================
// xd = xi_conv @ W_x^T  (N=33). 8 rows/block (64KB dyn smem)  (R6-verified)
// ============================================================================
constexpr int PRJ_ROWS = 8;
constexpr int PRJ_SMEM = PRJ_ROWS * DI * 4;   // 65536

__global__ void __launch_bounds__(256) projx_kernel(const float* __restrict__ W_x) {
    extern __shared__ float xs[];             // [PRJ_ROWS][DI]
    const int m0 = blockIdx.x * PRJ_ROWS;
    {
        const float4* src = (const float4*)(g_xiconv + (size_t)m0 * DI);
        float4* dst = (float4*)xs;
        for (int i = threadIdx.x; i < PRJ_ROWS * DI / 4; i += 256) dst[i] = src[i];
    }
    __syncthreads();

    const int warp = threadIdx.x >> 5;
    const int lane = threadIdx.x & 31;
    for (int g = warp; g < 9; g += 8) {
        const int nbase = g * 4;
        const int ncnt  = (g == 8) ? 1 : 4;
        float acc[4][PRJ_ROWS];
        #pragma unroll
        for (int a = 0; a < 4; a++)
            #pragma unroll
            for (int r = 0; r < PRJ_ROWS; r++) acc[a][r] = 0.f;

        for (int k = lane * 4; k < DI; k += 128) {
            float4 xr[PRJ_ROWS];
            #pragma unroll
            for (int r = 0; r < PRJ_ROWS; r++) xr[r] = *(const float4*)&xs[r * DI + k];
            for (int nn = 0; nn < ncnt; nn++) {
                float4 wv = *(const float4*)(W_x + (size_t)(nbase + nn) * DI + k);
                #pragma unroll
                for (int r = 0; r < PRJ_ROWS; r++) {
                    acc[nn][r] += wv.x * xr[r].x + wv.y * xr[r].y
                                + wv.z * xr[r].z + wv.w * xr[r].w;
                }
            }
        }
        for (int nn = 0; nn < ncnt; nn++) {
            #pragma unroll
            for (int r = 0; r < PRJ_ROWS; r++) {
                float v = acc[nn][r];
                #pragma unroll
                for (int off = 16; off; off >>= 1)
                    v += __shfl_xor_sync(0xffffffffu, v, off);
                acc[nn][r] = v;
            }
            if (lane == 0) {
                const int n = nbase + nn;
                #pragma unroll
                for (int r = 0; r < PRJ_ROWS; r++) {
                    int m = m0 + r;
                    if (n == 0)            g_dtraw[m] = acc[nn][r];
                    else if (n < 1 + DS)   g_Bc[m * DS + (n - 1)] = acc[nn][r];
                    else                   g_Cc[m * DS + (n - 1 - DS)] = acc[nn][r];
                }
            }
        }
    }
}

// ============================================================================
// selective scan: 8 threads per (b,d) channel, 2 states each, 8-deep register
// prefetch. Dense dt: per 8-step block, each lane computes softplus for its
// OWN channel at u == its sub index (1x work instead of 8x redundant), then
// steps fetch dt via intra-group shfl. Bit-identical math (verified: R10
// rel_err == R6 rel_err).
// ============================================================================
__global__ void __launch_bounds__(256) scan_kernel(const float* __restrict__ A_log,
                                                   const float* __restrict__ W_dt,
                                                   const float* __restrict__ b_dt) {
    const int lane = threadIdx.x & 31;
    const int sub  = threadIdx.x & 7;       // 8 subs per channel (== u index)
    const int dloc = threadIdx.x >> 3;      // 32 channels per block
    const int d    = blockIdx.x * 32 + dloc;
    const int b    = blockIdx.y;
    const int s0   = sub * 2;
    const int grpBase = lane & 24;          // first lane of this channel's group

    float Ac[2];
    #pragma unroll
    for (int i = 0; i < 2; i++) Ac[i] = -__expf(fminf(A_log[s0 + i], 5.f));
    const float Wd = W_dt[d];
    const float bd = b_dt[d];

    float h[2] = {0.f, 0.f};

    const size_t mbase = (size_t)b * LL;
    constexpr int PF = 8;
    float  dr_b[PF], xv_b[PF];
    float2 Bv_b[PF], Cv_b[PF];
    #pragma unroll
    for (int u = 0; u < PF; u++) {
        size_t m = mbase + u;
        dr_b[u] = g_dtraw[m];
        xv_b[u] = g_xiconv[m * DI + d];
        Bv_b[u] = *(const float2*)(g_Bc + m * DS + s0);
        Cv_b[u] = *(const float2*)(g_Cc + m * DS + s0);
    }

    for (int l0 = 0; l0 < LL; l0 += PF) {
        // dense dt precompute: this lane handles u == sub for its own channel
        float myDr = dr_b[0];
        #pragma unroll
        for (int u = 1; u < PF; u++) if (sub == u) myDr = dr_b[u];
        float xx = myDr * Wd + bd;
        float sp = fmaxf(xx, 0.f) + __logf(1.f + __expf(-fabsf(xx)));
        float myDt = fminf(fmaxf(sp, 1e-4f), 10.f);

        #pragma unroll
        for (int u = 0; u < PF; u++) {
            const int l = l0 + u;
            const float  xv = xv_b[u];
            const float2 Bq = Bv_b[u], Cq = Cv_b[u];
            const float dt = __shfl_sync(0xffffffffu, myDt, grpBase + u);

            const int lp = l + PF;
            if (lp < LL) {
                size_t mp = mbase + lp;
                dr_b[u] = g_dtraw[mp];
                xv_b[u] = g_xiconv[mp * DI + d];
                Bv_b[u] = *(const float2*)(g_Bc + mp * DS + s0);
                Cv_b[u] = *(const float2*)(g_Cc + mp * DS + s0);
            }

            float Bv[2] = {Bq.x, Bq.y};
            float Cv[2] = {Cq.x, Cq.y};
            float y = 0.f;
            #pragma unroll
            for (int i = 0; i < 2; i++) {
                // dt>0, Ac<0 -> dt*Ac<0 always; only the -20 clamp can bind
                float dA  = __expf(fmaxf(dt * Ac[i], -20.f));
                float dBu = fminf(fmaxf(dt * Bv[i] * xv, -10.f), 10.f);
                h[i] = fminf(fmaxf(h[i] * dA + dBu, -100.f), 100.f);
                y += h[i] * Cv[i];
            }
            y += __shfl_xor_sync(0xffffffffu, y, 1);
            y += __shfl_xor_sync(0xffffffffu, y, 2);
            y += __shfl_xor_sync(0xffffffffu, y, 4);
            if (sub == 0) g_y[(mbase + l) * DI + d] = y;
        }
    }
}

// ============================================================================
// layernorm(y) -> (yn + D*xi) * silu(z) -> bf16 hi/lo. y row cached in regs.
// ============================================================================
__device__ __forceinline__ float block_reduce_sum(float v) {
    __shared__ float sh[8];
    __syncthreads();
    int lane = threadIdx.x & 31, w = threadIdx.x >> 5;
    #pragma unroll
    for (int o = 16; o; o >>= 1) v += __shfl_xor_sync(0xffffffffu, v, o);
    if (lane == 0) sh[w] = v;
    __syncthreads();
    if (threadIdx.x < 32) {
        v = (threadIdx.x < 8) ? sh[threadIdx.x] : 0.f;
        #pragma unroll
        for (int o = 4; o; o >>= 1) v += __shfl_xor_sync(0xffffffffu, v, o);
        if (threadIdx.x == 0) sh[0] = v;
    }
    __syncthreads();
    return sh[0];
}

__global__ void __launch_bounds__(256) lncomb_kernel(const float* __restrict__ ln_w,
                                                     const float* __restrict__ ln_b,
                                                     const float* __restrict__ D_param) {
    const int m = blockIdx.x;
    const float* yrow = g_y + (size_t)m * DI;

    float4 yv[2];
    float s = 0.f;
    #pragma unroll
    for (int j = 0; j < 2; j++) {
        yv[j] = *(const float4*)(yrow + j * 1024 + threadIdx.x * 4);
        s += yv[j].x + yv[j].y + yv[j].z + yv[j].w;
    }
    float mu = block_reduce_sum(s) * (1.f / DI);

    float v = 0.f;
    #pragma unroll
    for (int j = 0; j < 2; j++) {
        float t0 = yv[j].x - mu, t1 = yv[j].y - mu, t2 = yv[j].z - mu, t3 = yv[j].w - mu;
        v += t0 * t0 + t1 * t1 + t2 * t2 + t3 * t3;
    }
    float var = block_reduce_sum(v) * (1.f / DI);
    float rstd = rsqrtf(var + 1e-5f);

    #pragma unroll
    for (int j = 0; j < 2; j++) {
        const int dd = j * 1024 + threadIdx.x * 4;
        float4 lw = *(const float4*)(ln_w + dd);
        float4 lb = *(const float4*)(ln_b + dd);
        float4 Dp = *(const float4*)(D_param + dd);
        float4 xi = *(const float4*)(g_xiconv + (size_t)m * DI + dd);
        float4 zz = *(const float4*)(g_xz + (size_t)m * NXZ + DI + dd);
        float yy[4] = {yv[j].x, yv[j].y, yv[j].z, yv[j].w};
        float lww[4] = {lw.x, lw.y, lw.z, lw.w};
        float lbb[4] = {lb.x, lb.y, lb.z, lb.w};
        float dpp[4] = {Dp.x, Dp.y, Dp.z, Dp.w};
        float xii[4] = {xi.x, xi.y, xi.z, xi.w};
        float zzz[4] = {zz.x, zz.y, zz.z, zz.w};
        __nv_bfloat16 hh[4], ll[4];
        #pragma unroll
        for (int q = 0; q < 4; q++) {
            float yn = (yy[q] - mu) * rstd * lww[q] + lbb[q];
            float sz = zzz[q] * (1.f / (1.f + __expf(-zzz[q])));
            float val = (yn + dpp[q] * xii[q]) * sz;
            hh[q] = __float2bfloat16(val);
            ll[q] = __float2bfloat16(val - __bfloat162float(hh[q]));
        }
        *(uint2*)(g_oph + (size_t)m * DI + dd) = *(uint2*)hh;
        *(uint2*)(g_opl + (size_t)m * DI + dd) = *(uint2*)ll;
    }
}

// ============================================================================
// launch
// ============================================================================
extern "C" void kernel_launch(void* const* d_in, const int* in_sizes, int n_in,
                              void* d_out, int out_size) {
    (void)in_sizes; (void)n_in; (void)out_size;
    const float* x       = (const float*)d_in[0];
    const float* W_in    = (const float*)d_in[1];
    const float* conv_w  = (const float*)d_in[2];
    const float* conv_b  = (const float*)d_in[3];
    const float* W_x     = (const float*)d_in[4];
    const float* W_dt    = (const float*)d_in[5];
    const float* b_dt    = (const float*)d_in[6];
    const float* A_log   = (const float*)d_in[7];
    const float* D_param = (const float*)d_in[8];
    const float* W_out   = (const float*)d_in[9];
    const float* ln_w    = (const float*)d_in[10];
    const float* ln_b    = (const float*)d_in[11];
    float* out = (float*)d_out;

    static __nv_bfloat16 *p_xh = nullptr, *p_xl, *p_wih, *p_wil, *p_oph, *p_opl, *p_woh, *p_wol;
    static float *p_xz = nullptr;
    if (!p_xh) {
        cudaGetSymbolAddress((void**)&p_xh,  g_xh);
        cudaGetSymbolAddress((void**)&p_xl,  g_xl);
        cudaGetSymbolAddress((void**)&p_wih, g_wih);
        cudaGetSymbolAddress((void**)&p_wil, g_wil);
        cudaGetSymbolAddress((void**)&p_oph, g_oph);
        cudaGetSymbolAddress((void**)&p_opl, g_opl);
        cudaGetSymbolAddress((void**)&p_woh, g_woh);
        cudaGetSymbolAddress((void**)&p_wol, g_wol);
        cudaGetSymbolAddress((void**)&p_xz,  g_xz);
        cudaFuncSetAttribute(gemm_mma<NXZ, DM>,
                             cudaFuncAttributeMaxDynamicSharedMemorySize, GEMM_SMEM);
        cudaFuncSetAttribute(gemm_mma<DM, DI>,
                             cudaFuncAttributeMaxDynamicSharedMemorySize, GEMM_SMEM);
        cudaFuncSetAttribute(projx_kernel,
                             cudaFuncAttributeMaxDynamicSharedMemorySize, PRJ_SMEM);
    }

    // 0) fp32 -> bf16 hi/lo splits for x, W_in, W_out (ONE launch)
    split_all_kernel<<<(N4_TOT + 255) / 256, 256>>>(x, W_in, W_out,
                                                    p_xh, p_xl, p_wih, p_wil,
                                                    p_woh, p_wol);

    // 1) xz = x @ W_in^T   (mma.sync, bf16-split)
    {
        dim3 grid(NXZ / 128, MR / 128);
        gemm_mma<NXZ, DM><<<grid, 256, GEMM_SMEM>>>(p_xh, p_xl, p_wih, p_wil, p_xz);
    }
    // 2) conv + silu
    conv_silu_kernel<<<(MR * DI) / 256, 256>>>(conv_w, conv_b);
    // 3) xd projection (dtraw, B, C)
    projx_kernel<<<MR / PRJ_ROWS, 256, PRJ_SMEM>>>(W_x);
    // 4) sequential selective scan (dense dt)
    {
        dim3 grid(DI / 32, BB);
        scan_kernel<<<grid, 256>>>(A_log, W_dt, b_dt);
    }
    // 5) layernorm + combine (writes bf16 hi/lo outpre)
    lncomb_kernel<<<MR, 256>>>(ln_w, ln_b, D_param);
    // 6) out = outpre @ W_out^T   (mma.sync, bf16-split)
    {
        dim3 grid(DM / 128, MR / 128);
        gemm_mma<DM, DI><<<grid, 256, GEMM_SMEM>>>(p_oph, p_opl, p_woh, p_wol, out);
    }
}

// round 13
// speedup vs baseline: 1.0858x; 1.0661x over previous
#include <cuda_runtime.h>
#include <cuda_bf16.h>
#include <cstdint>

// ---------------- problem constants ----------------
constexpr int BB = 4;
constexpr int LL = 2048;
constexpr int DM = 1024;
constexpr int DI = 2048;      // d_inner
constexpr int DS = 16;        // d_state
constexpr int MR = BB * LL;   // 8192 rows
constexpr int NXZ = 2 * DI;   // 4096
constexpr int NP  = 128;      // padded xd width (33 real columns)

// ---------------- scratch (device globals; no allocation allowed) ----------------
__device__ float g_xz[(size_t)MR * NXZ];       // [xi | z]
__device__ float g_xiconv[(size_t)MR * DI];    // silu(conv(xi))
__device__ float g_dtraw[MR];
__device__ float g_Bc[MR * DS];
__device__ float g_Cc[MR * DS];
__device__ float g_y[(size_t)MR * DI];
__device__ float g_xd[(size_t)MR * NP];        // padded projection output

// bf16 hi/lo split operands for the tensor-core GEMMs
__device__ __nv_bfloat16 g_xh [(size_t)MR * DM];
__device__ __nv_bfloat16 g_xl [(size_t)MR * DM];
__device__ __nv_bfloat16 g_wih[(size_t)NXZ * DM];
__device__ __nv_bfloat16 g_wil[(size_t)NXZ * DM];
__device__ __nv_bfloat16 g_oph[(size_t)MR * DI];
__device__ __nv_bfloat16 g_opl[(size_t)MR * DI];
__device__ __nv_bfloat16 g_woh[(size_t)DM * DI];
__device__ __nv_bfloat16 g_wol[(size_t)DM * DI];
__device__ __nv_bfloat16 g_xch[(size_t)MR * DI];   // xiconv hi
__device__ __nv_bfloat16 g_xcl[(size_t)MR * DI];   // xiconv lo
__device__ __nv_bfloat16 g_wxh[(size_t)NP * DI];   // W_x padded hi
__device__ __nv_bfloat16 g_wxl[(size_t)NP * DI];   // W_x padded lo

// ============================================================================
// PTX helpers (portable sm_80+ subset only — NO tcgen05 on this build target)
// ============================================================================
__device__ __forceinline__ uint32_t smem_u32(const void* p) {
    uint32_t a;
    asm("{ .reg .u64 t; cvta.to.shared.u64 t, %1; cvt.u32.u64 %0, t; }" : "=r"(a) : "l"(p));
    return a;
}
__device__ __forceinline__ void cp_async16(uint32_t dst, const void* src) {
    asm volatile("cp.async.cg.shared.global [%0], [%1], 16;" :: "r"(dst), "l"(src));
}
__device__ __forceinline__ void cp_commit() { asm volatile("cp.async.commit_group;"); }
template<int N> __device__ __forceinline__ void cp_wait() {
    asm volatile("cp.async.wait_group %0;" :: "n"(N));
}
__device__ __forceinline__ void ldmx4(uint32_t& r0, uint32_t& r1, uint32_t& r2, uint32_t& r3,
                                      uint32_t addr) {
    asm volatile("ldmatrix.sync.aligned.m8n8.x4.shared.b16 {%0,%1,%2,%3}, [%4];"
                 : "=r"(r0), "=r"(r1), "=r"(r2), "=r"(r3) : "r"(addr));
}
__device__ __forceinline__ void mma_bf16(float* c, const uint32_t* a, const uint32_t* b) {
    asm volatile(
        "mma.sync.aligned.m16n8k16.row.col.f32.bf16.bf16.f32 "
        "{%0,%1,%2,%3}, {%4,%5,%6,%7}, {%8,%9}, {%0,%1,%2,%3};"
        : "+f"(c[0]), "+f"(c[1]), "+f"(c[2]), "+f"(c[3])
        : "r"(a[0]), "r"(a[1]), "r"(a[2]), "r"(a[3]), "r"(b[0]), "r"(b[1]));
}
// SW64 swizzle on byte offsets within a (128-row x 64B) tile. 16B-granular.
__device__ __forceinline__ uint32_t swz64(uint32_t off) {
    return off ^ ((off >> 3) & 0x30);
}

// ============================================================================
// bf16-split mma.sync GEMM (EXACT R6 schedule — verified local optimum):
// Block 128x128, BK=32, 8 warps (2x4), warp tile 64x32.
// SW64-swizzled 64B rows; 3-stage cp.async; per-kk B loads; load AFTER compute.
// ============================================================================
constexpr int ROWB   = 64;
constexpr int TILEB  = 128 * ROWB;          // 8192 per operand tile
constexpr int STAGEB = 4 * TILEB;           // 32768
constexpr int NSTAGE = 3;
constexpr int GEMM_SMEM = NSTAGE * STAGEB;  // 98304

template<int Ktot>
__device__ __forceinline__ void load_stage(uint32_t stage, int k0, int bm0, int bn0,
                                           const __nv_bfloat16* __restrict__ Ah,
                                           const __nv_bfloat16* __restrict__ Al,
                                           const __nv_bfloat16* __restrict__ Bh,
                                           const __nv_bfloat16* __restrict__ Bl,
                                           int tid) {
    const __nv_bfloat16* srcs[4] = {Ah, Al, Bh, Bl};
    const int row0s[2] = {bm0, bn0};
    #pragma unroll
    for (int i = 0; i < 8; i++) {
        int u = tid + i * 256;
        int s = u >> 9;
        int v = u & 511;
        int r = v >> 2, c = v & 3;
        cp_async16(stage + s * TILEB + swz64(r * ROWB + c * 16),
                   srcs[s] + (size_t)(row0s[s >> 1] + r) * Ktot + k0 + c * 8);
    }
    cp_commit();
}

template<int Ntot, int Ktot>
__global__ void __launch_bounds__(256) gemm_mma(const __nv_bfloat16* __restrict__ Ah,
                                                const __nv_bfloat16* __restrict__ Al,
                                                const __nv_bfloat16* __restrict__ Bh,
                                                const __nv_bfloat16* __restrict__ Bl,
                                                float* __restrict__ C) {
    extern __shared__ char smem[];
    const uint32_t sb = smem_u32(smem);
    const int tid  = threadIdx.x;
    const int wid  = tid >> 5, lane = tid & 31;
    const int wm   = wid >> 2;
    const int wn   = wid & 3;
    const int bm0  = blockIdx.y * 128;
    const int bn0  = blockIdx.x * 128;
    constexpr int NCHUNK = Ktot / 32;

    float acc[4][4][4];
    #pragma unroll
    for (int i = 0; i < 4; i++)
        #pragma unroll
        for (int j = 0; j < 4; j++)
            #pragma unroll
            for (int q = 0; q < 4; q++) acc[i][j][q] = 0.f;

    const int lrow  = lane & 15;
    const int khalf = (lane >> 4) * 16;
    const uint32_t aRow = (wm * 64 + lrow) * ROWB;
    const uint32_t bRow = (wn * 32 + lrow) * ROWB;

    load_stage<Ktot>(sb, 0, bm0, bn0, Ah, Al, Bh, Bl, tid);
    load_stage<Ktot>(sb + STAGEB, 32, bm0, bn0, Ah, Al, Bh, Bl, tid);

    uint32_t stOff = 0;
    uint32_t ldOff = 2 * STAGEB;

    for (int k = 0; k < NCHUNK; k++) {
        if (k + 1 < NCHUNK) cp_wait<1>(); else cp_wait<0>();
        __syncthreads();

        const uint32_t st = sb + stOff;
        #pragma unroll
        for (int kk = 0; kk < 32; kk += 16) {
            const uint32_t kbyte = kk * 2 + khalf;
            uint32_t bh[8], bl[8];
            #pragma unroll
            for (int nj = 0; nj < 2; nj++) {
                uint32_t a = st + 2 * TILEB + swz64(bRow + nj * 16 * ROWB + kbyte);
                ldmx4(bh[nj * 4 + 0], bh[nj * 4 + 1], bh[nj * 4 + 2], bh[nj * 4 + 3], a);
                ldmx4(bl[nj * 4 + 0], bl[nj * 4 + 1], bl[nj * 4 + 2], bl[nj * 4 + 3], a + TILEB);
            }
            #pragma unroll
            for (int mi = 0; mi < 4; mi++) {
                uint32_t ah[4], al[4];
                uint32_t a = st + swz64(aRow + mi * 16 * ROWB + kbyte);
                ldmx4(ah[0], ah[1], ah[2], ah[3], a);
                ldmx4(al[0], al[1], al[2], al[3], a + TILEB);
                #pragma unroll
                for (int ni = 0; ni < 4; ni++) {
                    const int g = (ni >> 1) * 4 + (ni & 1);
                    uint32_t bhp[2] = {bh[g], bh[g + 2]};
                    uint32_t blp[2] = {bl[g], bl[g + 2]};
                    mma_bf16(acc[mi][ni], ah, bhp);
                    mma_bf16(acc[mi][ni], ah, blp);
                    mma_bf16(acc[mi][ni], al, bhp);
                }
            }
        }
        if (k + 2 < NCHUNK) {
            load_stage<Ktot>(sb + ldOff, (k + 2) * 32, bm0, bn0, Ah, Al, Bh, Bl, tid);
            ldOff += STAGEB; if (ldOff == NSTAGE * STAGEB) ldOff = 0;
        }
        stOff += STAGEB; if (stOff == NSTAGE * STAGEB) stOff = 0;
    }

    #pragma unroll
    for (int mi = 0; mi < 4; mi++) {
        const int r0 = bm0 + wm * 64 + mi * 16 + (lane >> 2);
        #pragma unroll
        for (int ni = 0; ni < 4; ni++) {
            const int c = bn0 + wn * 32 + ni * 8 + (lane & 3) * 2;
            *(float2*)(C + (size_t)r0 * Ntot + c) =
                make_float2(acc[mi][ni][0], acc[mi][ni][1]);
            *(float2*)(C + (size_t)(r0 + 8) * Ntot + c) =
                make_float2(acc[mi][ni][2], acc[mi][ni][3]);
        }
    }
}

// ============================================================================
// merged fp32 -> bf16 hi/lo split for x, W_in, W_out in ONE launch
// ============================================================================
constexpr int N4_X  = MR * DM / 4;
constexpr int N4_WI = NXZ * DM / 4;
constexpr int N4_WO = DM * DI / 4;
constexpr int N4_TOT = N4_X + N4_WI + N4_WO;

__global__ void __launch_bounds__(256) split_all_kernel(const float* __restrict__ x,
                                                        const float* __restrict__ W_in,
                                                        const float* __restrict__ W_out,
                                                        __nv_bfloat16* __restrict__ xh,
                                                        __nv_bfloat16* __restrict__ xl,
                                                        __nv_bfloat16* __restrict__ wih,
                                                        __nv_bfloat16* __restrict__ wil,
                                                        __nv_bfloat16* __restrict__ woh,
                                                        __nv_bfloat16* __restrict__ wol) {
    int i = blockIdx.x * 256 + threadIdx.x;
    if (i >= N4_TOT) return;
    const float* src;
    __nv_bfloat16 *hi, *lo;
    int j;
    if (i < N4_X)              { src = x;     hi = xh;  lo = xl;  j = i; }
    else if (i < N4_X + N4_WI) { src = W_in;  hi = wih; lo = wil; j = i - N4_X; }
    else                       { src = W_out; hi = woh; lo = wol; j = i - N4_X - N4_WI; }

    float4 v = *(const float4*)(src + (size_t)j * 4);
    float vv[4] = {v.x, v.y, v.z, v.w};
    __nv_bfloat16 h[4], l[4];
    #pragma unroll
    for (int q = 0; q < 4; q++) {
        h[q] = __float2bfloat16(vv[q]);
        l[q] = __float2bfloat16(vv[q] - __bfloat162float(h[q]));
    }
    *(uint2*)(hi + (size_t)j * 4) = *(uint2*)h;
    *(uint2*)(lo + (size_t)j * 4) = *(uint2*)l;
}

// ============================================================================
// W_x split + zero-pad to [NP=128, DI] bf16 hi/lo (rows 33..127 zero)
// ============================================================================
__global__ void __launch_bounds__(256) split_wx_kernel(const float* __restrict__ W_x) {
    int i = blockIdx.x * 256 + threadIdx.x;       // float4 index over NP*DI/4
    if (i >= NP * DI / 4) return;
    int row = i / (DI / 4);
    __nv_bfloat16 h[4] = {}, l[4] = {};
    if (row < 2 * DS + 1) {
        float4 v = *(const float4*)(W_x + (size_t)i * 4);
        float vv[4] = {v.x, v.y, v.z, v.w};
        #pragma unroll
        for (int q = 0; q < 4; q++) {
            h[q] = __float2bfloat16(vv[q]);
            l[q] = __float2bfloat16(vv[q] - __bfloat162float(h[q]));
        }
    }
    *(uint2*)(g_wxh + (size_t)i * 4) = *(uint2*)h;
    *(uint2*)(g_wxl + (size_t)i * 4) = *(uint2*)l;
}

// ============================================================================
// causal depthwise conv (k=4, pad left 3) + bias + silu, ALSO emitting
// bf16 hi/lo of xiconv for the projx tensor-core GEMM
// ============================================================================
__global__ void __launch_bounds__(256) conv_silu_kernel(const float* __restrict__ conv_w,
                                                        const float* __restrict__ conv_b) {
    int idx = blockIdx.x * 256 + threadIdx.x;
    if (idx >= MR * DI) return;
    int c = idx & (DI - 1);
    int m = idx >> 11;
    int l = m & (LL - 1);

    float4 w4 = *(const float4*)(conv_w + c * 4);
    float w[4] = {w4.x, w4.y, w4.z, w4.w};
    const float* base = g_xz + (size_t)m * NXZ + c;
    float s = conv_b[c];
    #pragma unroll
    for (int t = 0; t < 4; t++) {
        int ll = l - 3 + t;
        if (ll >= 0) s += base[(ptrdiff_t)(t - 3) * NXZ] * w[t];
    }
    float sv = s * (1.f / (1.f + __expf(-s)));
    g_xiconv[idx] = sv;
    __nv_bfloat16 hh = __float2bfloat16(sv);
    g_xch[idx] = hh;
    g_xcl[idx] = __float2bfloat16(sv - __bfloat162float(hh));
}

// ============================================================================
// gather: xd[m][0]->dtraw, [1..16]->Bc, [17..32]->Cc
// ============================================================================
__global__ void __launch_bounds__(256) gather_xd_kernel() {
    int i = blockIdx.x * 256 + threadIdx.x;       // over MR * 33
    if (i >= MR * 33) return;
    int m = i / 33;
    int n = i - m * 33;
    float v = g_xd[(size_t)m * NP + n];
    if (n == 0)          g_dtraw[m] = v;
    else if (n < 1 + DS) g_Bc[m * DS + (n - 1)] = v;
    else                 g_Cc[m * DS + (n - 1 - DS)] = v;
}

// ============================================================================
// selective scan (EXACT R6 form): 8 threads per (b,d) channel, 2 states each,
// 8-deep register prefetch, per-thread fused softplus dt.
// ============================================================================
__global__ void __launch_bounds__(256) scan_kernel(const float* __restrict__ A_log,
                                                   const float* __restrict__ W_dt,
                                                   const float* __restrict__ b_dt) {
    const int sub  = threadIdx.x & 7;
    const int dloc = threadIdx.x >> 3;
    const int d    = blockIdx.x * 32 + dloc;
    const int b    = blockIdx.y;
    const int s0   = sub * 2;

    float Ac[2];
    #pragma unroll
    for (int i = 0; i < 2; i++) Ac[i] = -__expf(fminf(A_log[s0 + i], 5.f));
    const float Wd = W_dt[d];
    const float bd = b_dt[d];

    float h[2] = {0.f, 0.f};

    const size_t mbase = (size_t)b * LL;
    constexpr int PF = 8;
    float  dr_b[PF], xv_b[PF];
    float2 Bv_b[PF], Cv_b[PF];
    #pragma unroll
    for (int u = 0; u < PF; u++) {
        size_t m = mbase + u;
        dr_b[u] = g_dtraw[m];
        xv_b[u] = g_xiconv[m * DI + d];
        Bv_b[u] = *(const float2*)(g_Bc + m * DS + s0);
        Cv_b[u] = *(const float2*)(g_Cc + m * DS + s0);
    }

    for (int l0 = 0; l0 < LL; l0 += PF) {
        #pragma unroll
        for (int u = 0; u < PF; u++) {
            const int l = l0 + u;
            const float  dr = dr_b[u], xv = xv_b[u];
            const float2 Bq = Bv_b[u], Cq = Cv_b[u];

            const int lp = l + PF;
            if (lp < LL) {
                size_t mp = mbase + lp;
                dr_b[u] = g_dtraw[mp];
                xv_b[u] = g_xiconv[mp * DI + d];
                Bv_b[u] = *(const float2*)(g_Bc + mp * DS + s0);
                Cv_b[u] = *(const float2*)(g_Cc + mp * DS + s0);
            }

            float xx = dr * Wd + bd;
            float sp = fmaxf(xx, 0.f) + __logf(1.f + __expf(-fabsf(xx)));
            float dt = fminf(fmaxf(sp, 1e-4f), 10.f);

            float Bv[2] = {Bq.x, Bq.y};
            float Cv[2] = {Cq.x, Cq.y};
            float y = 0.f;
            #pragma unroll
            for (int i = 0; i < 2; i++) {
                float dA  = __expf(fmaxf(fminf(dt * Ac[i], 0.f), -20.f));
                float dBu = fminf(fmaxf(dt * Bv[i] * xv, -10.f), 10.f);
                h[i] = fminf(fmaxf(h[i] * dA + dBu, -100.f), 100.f);
                y += h[i] * Cv[i];
            }
            y += __shfl_xor_sync(0xffffffffu, y, 1);
            y += __shfl_xor_sync(0xffffffffu, y, 2);
            y += __shfl_xor_sync(0xffffffffu, y, 4);
            if (sub == 0) g_y[(mbase + l) * DI + d] = y;
        }
    }
}

// ============================================================================
// layernorm(y) -> (yn + D*xi) * silu(z) -> bf16 hi/lo. y row cached in regs.
// ============================================================================
__device__ __forceinline__ float block_reduce_sum(float v) {
    __shared__ float sh[8];
    __syncthreads();
    int lane = threadIdx.x & 31, w = threadIdx.x >> 5;
    #pragma unroll
    for (int o = 16; o; o >>= 1) v += __shfl_xor_sync(0xffffffffu, v, o);
    if (lane == 0) sh[w] = v;
    __syncthreads();
    if (threadIdx.x < 32) {
        v = (threadIdx.x < 8) ? sh[threadIdx.x] : 0.f;
        #pragma unroll
        for (int o = 4; o; o >>= 1) v += __shfl_xor_sync(0xffffffffu, v, o);
        if (threadIdx.x == 0) sh[0] = v;
    }
    __syncthreads();
    return sh[0];
}

__global__ void __launch_bounds__(256) lncomb_kernel(const float* __restrict__ ln_w,
                                                     const float* __restrict__ ln_b,
                                                     const float* __restrict__ D_param) {
    const int m = blockIdx.x;
    const float* yrow = g_y + (size_t)m * DI;

    float4 yv[2];
    float s = 0.f;
    #pragma unroll
    for (int j = 0; j < 2; j++) {
        yv[j] = *(const float4*)(yrow + j * 1024 + threadIdx.x * 4);
        s += yv[j].x + yv[j].y + yv[j].z + yv[j].w;
    }
    float mu = block_reduce_sum(s) * (1.f / DI);

    float v = 0.f;
    #pragma unroll
    for (int j = 0; j < 2; j++) {
        float t0 = yv[j].x - mu, t1 = yv[j].y - mu, t2 = yv[j].z - mu, t3 = yv[j].w - mu;
        v += t0 * t0 + t1 * t1 + t2 * t2 + t3 * t3;
    }
    float var = block_reduce_sum(v) * (1.f / DI);
    float rstd = rsqrtf(var + 1e-5f);

    #pragma unroll
    for (int j = 0; j < 2; j++) {
        const int dd = j * 1024 + threadIdx.x * 4;
        float4 lw = *(const float4*)(ln_w + dd);
        float4 lb = *(const float4*)(ln_b + dd);
        float4 Dp = *(const float4*)(D_param + dd);
        float4 xi = *(const float4*)(g_xiconv + (size_t)m * DI + dd);
        float4 zz = *(const float4*)(g_xz + (size_t)m * NXZ + DI + dd);
        float yy[4] = {yv[j].x, yv[j].y, yv[j].z, yv[j].w};
        float lww[4] = {lw.x, lw.y, lw.z, lw.w};
        float lbb[4] = {lb.x, lb.y, lb.z, lb.w};
        float dpp[4] = {Dp.x, Dp.y, Dp.z, Dp.w};
        float xii[4] = {xi.x, xi.y, xi.z, xi.w};
        float zzz[4] = {zz.x, zz.y, zz.z, zz.w};
        __nv_bfloat16 hh[4], ll[4];
        #pragma unroll
        for (int q = 0; q < 4; q++) {
            float yn = (yy[q] - mu) * rstd * lww[q] + lbb[q];
            float sz = zzz[q] * (1.f / (1.f + __expf(-zzz[q])));
            float val = (yn + dpp[q] * xii[q]) * sz;
            hh[q] = __float2bfloat16(val);
            ll[q] = __float2bfloat16(val - __bfloat162float(hh[q]));
        }
        *(uint2*)(g_oph + (size_t)m * DI + dd) = *(uint2*)hh;
        *(uint2*)(g_opl + (size_t)m * DI + dd) = *(uint2*)ll;
    }
}

// ============================================================================
// launch
// ============================================================================
extern "C" void kernel_launch(void* const* d_in, const int* in_sizes, int n_in,
                              void* d_out, int out_size) {
    (void)in_sizes; (void)n_in; (void)out_size;
    const float* x       = (const float*)d_in[0];
    const float* W_in    = (const float*)d_in[1];
    const float* conv_w  = (const float*)d_in[2];
    const float* conv_b  = (const float*)d_in[3];
    const float* W_x     = (const float*)d_in[4];
    const float* W_dt    = (const float*)d_in[5];
    const float* b_dt    = (const float*)d_in[6];
    const float* A_log   = (const float*)d_in[7];
    const float* D_param = (const float*)d_in[8];
    const float* W_out   = (const float*)d_in[9];
    const float* ln_w    = (const float*)d_in[10];
    const float* ln_b    = (const float*)d_in[11];
    float* out = (float*)d_out;

    static __nv_bfloat16 *p_xh = nullptr, *p_xl, *p_wih, *p_wil, *p_oph, *p_opl, *p_woh, *p_wol;
    static __nv_bfloat16 *p_xch, *p_xcl, *p_wxh, *p_wxl;
    static float *p_xz = nullptr, *p_xd;
    if (!p_xh) {
        cudaGetSymbolAddress((void**)&p_xh,  g_xh);
        cudaGetSymbolAddress((void**)&p_xl,  g_xl);
        cudaGetSymbolAddress((void**)&p_wih, g_wih);
        cudaGetSymbolAddress((void**)&p_wil, g_wil);
        cudaGetSymbolAddress((void**)&p_oph, g_oph);
        cudaGetSymbolAddress((void**)&p_opl, g_opl);
        cudaGetSymbolAddress((void**)&p_woh, g_woh);
        cudaGetSymbolAddress((void**)&p_wol, g_wol);
        cudaGetSymbolAddress((void**)&p_xch, g_xch);
        cudaGetSymbolAddress((void**)&p_xcl, g_xcl);
        cudaGetSymbolAddress((void**)&p_wxh, g_wxh);
        cudaGetSymbolAddress((void**)&p_wxl, g_wxl);
        cudaGetSymbolAddress((void**)&p_xz,  g_xz);
        cudaGetSymbolAddress((void**)&p_xd,  g_xd);
        cudaFuncSetAttribute(gemm_mma<NXZ, DM>,
                             cudaFuncAttributeMaxDynamicSharedMemorySize, GEMM_SMEM);
        cudaFuncSetAttribute(gemm_mma<DM, DI>,
                             cudaFuncAttributeMaxDynamicSharedMemorySize, GEMM_SMEM);
        cudaFuncSetAttribute(gemm_mma<NP, DI>,
                             cudaFuncAttributeMaxDynamicSharedMemorySize, GEMM_SMEM);
    }

    // 0) fp32 -> bf16 hi/lo splits for x, W_in, W_out (one launch) + W_x pad
    split_all_kernel<<<(N4_TOT + 255) / 256, 256>>>(x, W_in, W_out,
                                                    p_xh, p_xl, p_wih, p_wil,
                                                    p_woh, p_wol);
    split_wx_kernel<<<(NP * DI / 4 + 255) / 256, 256>>>(W_x);

    // 1) xz = x @ W_in^T   (mma.sync, bf16-split)
    {
        dim3 grid(NXZ / 128, MR / 128);
        gemm_mma<NXZ, DM><<<grid, 256, GEMM_SMEM>>>(p_xh, p_xl, p_wih, p_wil, p_xz);
    }
    // 2) conv + silu (also emits bf16 hi/lo xiconv)
    conv_silu_kernel<<<(MR * DI) / 256, 256>>>(conv_w, conv_b);
    // 3) xd = xiconv @ W_x_pad^T   (tensor cores, N padded to 128)
    {
        dim3 grid(1, MR / 128);
        gemm_mma<NP, DI><<<grid, 256, GEMM_SMEM>>>(p_xch, p_xcl, p_wxh, p_wxl, p_xd);
    }
    // 3b) scatter xd -> dtraw / Bc / Cc
    gather_xd_kernel<<<(MR * 33 + 255) / 256, 256>>>();
    // 4) sequential selective scan (R6 form)
    {
        dim3 grid(DI / 32, BB);
        scan_kernel<<<grid, 256>>>(A_log, W_dt, b_dt);
    }
    // 5) layernorm + combine (writes bf16 hi/lo outpre)
    lncomb_kernel<<<MR, 256>>>(ln_w, ln_b, D_param);
    // 6) out = outpre @ W_out^T   (mma.sync, bf16-split)
    {
        dim3 grid(DM / 128, MR / 128);
        gemm_mma<DM, DI><<<grid, 256, GEMM_SMEM>>>(p_oph, p_opl, p_woh, p_wol, out);
    }
}